// round 9
// baseline (speedup 1.0000x reference)
#include <cuda_runtime.h>
#include <cuda_bf16.h>
#include <cstdint>

#define B     2
#define N     4096
#define QD    1024
#define CD    1024
#define H     8
#define DH    64
#define INNER 512
#define NK    4097
#define NKP   4224
typedef long long ll;
typedef __nv_bfloat16 bf;

// ---------------- device scratch ----------------
__device__ __align__(16) bf g_xs[2][B*N*QD];
__device__ __align__(16) bf g_cs[2][B*N*CD];
__device__ __align__(16) bf g_wq[2][QD*INNER];
__device__ __align__(16) bf g_wk[2][CD*INNER];
__device__ __align__(16) bf g_wv[2][CD*INNER];
__device__ __align__(16) bf g_wo[2][INNER*QD];
__device__ __align__(16) bf g_q [2][B*N*INNER];
__device__ __align__(16) bf g_vd[2][B*NKP*INNER];    // dense v
__device__ __align__(16) bf g_kd[2][B*NKP*INNER];    // dense k
__device__ __align__(16) bf g_vt[2][B*H*DH*NKP];     // dense v, transposed
__device__ __align__(16) bf g_ao[2][B*N*INNER];
__device__ float g_ppart[16][B*QD];
__device__ float g_pooled[B*QD];
__device__ int g_gidx[B*NKP];     // dense -> orig
__device__ int g_scat[B*NKP];     // orig -> dense (or -1)
__device__ int g_nvalid[B];

// ---------------- helpers ----------------
__device__ __forceinline__ uint32_t sm_u32(const void* p){
    uint32_t a;
    asm("{ .reg .u64 t; cvta.to.shared.u64 t, %1; cvt.u32.u64 %0, t; }" : "=r"(a) : "l"(p));
    return a;
}
__device__ __forceinline__ void ldmx4(uint32_t* r, uint32_t addr){
    asm volatile("ldmatrix.sync.aligned.m8n8.x4.shared.b16 {%0,%1,%2,%3}, [%4];"
        : "=r"(r[0]), "=r"(r[1]), "=r"(r[2]), "=r"(r[3]) : "r"(addr));
}
__device__ __forceinline__ void mma16816(float* d, const uint32_t* a, const uint32_t* b){
    asm volatile("mma.sync.aligned.m16n8k16.row.col.f32.bf16.bf16.f32 "
        "{%0,%1,%2,%3}, {%4,%5,%6,%7}, {%8,%9}, {%0,%1,%2,%3};"
        : "+f"(d[0]), "+f"(d[1]), "+f"(d[2]), "+f"(d[3])
        : "r"(a[0]), "r"(a[1]), "r"(a[2]), "r"(a[3]), "r"(b[0]), "r"(b[1]));
}
#define CP_ASYNC(dst, src) \
    asm volatile("cp.async.cg.shared.global [%0], [%1], 16;" :: "r"(dst), "l"(src))
#define CP_COMMIT() asm volatile("cp.async.commit_group;" ::: "memory")
#define CP_WAIT1()  asm volatile("cp.async.wait_group 1;" ::: "memory")
#define CP_WAIT0()  asm volatile("cp.async.wait_group 0;" ::: "memory")

__device__ __forceinline__ uint32_t packbf(float a, float b){
    uint32_t r;
    asm("cvt.rn.bf16x2.f32 %0, %1, %2;" : "=r"(r) : "f"(b), "f"(a));
    return r;
}
__device__ __forceinline__ uint32_t packbf_lo(float a, float b, uint32_t hi){
    float hx = __uint_as_float((hi & 0xFFFFu) << 16);
    float hy = __uint_as_float(hi & 0xFFFF0000u);
    return packbf(a - hx, b - hy);
}
__device__ __forceinline__ float fexp(float x){
    float t = fmaxf(x * 1.4426950409f, -120.f);
    float r = rintf(t);
    float f = t - r;
    float p = 1.33336e-3f;
    p = fmaf(p, f, 9.61812e-3f);
    p = fmaf(p, f, 5.55041e-2f);
    p = fmaf(p, f, 2.4022651e-1f);
    p = fmaf(p, f, 6.9314718e-1f);
    p = fmaf(p, f, 1.0f);
    return p * __int_as_float(((int)r + 127) << 23);
}

// ---------------- mask scan ----------------
__global__ void scan_kernel(const unsigned char* __restrict__ m){
    __shared__ int anynz;
    __shared__ int sc[256];
    int tid = threadIdx.x, b = blockIdx.x;
    if (tid == 0) anynz = 0;
    __syncthreads();
    int loc = 0;
    for (int i = tid; i < 8192; i += 256)
        if ((i & 3) && m[i]) loc = 1;
    if (loc) atomicOr(&anynz, 1);
    __syncthreads();
    bool u8 = (anynz != 0);
    const int* mi = (const int*)m;

    int base = tid * 17, c = 0;
    unsigned int bits = 0;
    #pragma unroll
    for (int e = 0; e < 17; e++){
        int w = base + e;
        int on = 0;
        if (w < NK) on = u8 ? (m[b*NK + w] != 0) : (mi[b*NK + w] != 0);
        bits |= (unsigned)on << e;
        c += on;
    }
    sc[tid] = c;
    __syncthreads();
    for (int off = 1; off < 256; off <<= 1){
        int v = (tid >= off) ? sc[tid - off] : 0;
        __syncthreads();
        sc[tid] += v;
        __syncthreads();
    }
    int pos = sc[tid] - c;
    #pragma unroll
    for (int e = 0; e < 17; e++){
        int w = base + e;
        if (w < NKP){
            if ((bits >> e) & 1){
                g_gidx[b*NKP + pos] = w;
                g_scat[b*NKP + w] = pos;
                pos++;
            } else {
                g_scat[b*NKP + w] = -1;
            }
        }
    }
    __syncthreads();
    int nvv = sc[255];
    if (tid == 0) g_nvalid[b] = nvv;
    for (int i = nvv + tid; i < NKP; i += 256) g_gidx[b*NKP + i] = 0;   // clamp tail
}

// ---------------- pooled mean ----------------
__global__ void pooled_p1(const float* __restrict__ x){
    int id = blockIdx.x*256 + threadIdx.x;
    int chunk = blockIdx.y;
    int b = id / QD, d = id % QD;
    const float* p = x + (size_t)b*N*QD + (size_t)chunk*256*QD + d;
    float s = 0.f;
    #pragma unroll 8
    for (int n = 0; n < 256; n++) s += p[(size_t)n*QD];
    g_ppart[chunk][id] = s;
}
__global__ void pooled_p2(){
    int id = blockIdx.x*256 + threadIdx.x;
    if (id >= B*QD) return;
    float s = 0.f;
    #pragma unroll
    for (int c = 0; c < 16; c++) s += g_ppart[c][id];
    g_pooled[id] = s * (1.0f/N);
}

__global__ void bg_kernel(const float* __restrict__ Wkbg, const float* __restrict__ Wvbg){
    int id = blockIdx.x*256 + threadIdx.x;
    if (id >= B*INNER) return;
    int b = id / INNER, o = id % INNER;
    int pos = g_scat[b*NKP + N];
    if (pos < 0) return;
    float sk = 0.f, sv = 0.f;
    for (int k = 0; k < QD; k++){
        float pv = g_pooled[b*QD + k];
        sk += pv * Wkbg[(size_t)k*INNER + o];
        sv += pv * Wvbg[(size_t)k*INNER + o];
    }
    size_t kb = (size_t)(b*NKP + pos)*INNER + o;
    bf h;
    h = __float2bfloat16(sk); g_kd[0][kb] = h; g_kd[1][kb] = __float2bfloat16(sk - __bfloat162float(h));
    h = __float2bfloat16(sv); g_vd[0][kb] = h; g_vd[1][kb] = __float2bfloat16(sv - __bfloat162float(h));
}

__global__ void pack_split(const float4* __restrict__ src, bf* __restrict__ hi, bf* __restrict__ lo, int n4){
    int i = blockIdx.x*256 + threadIdx.x;
    if (i >= n4) return;
    float4 v = src[i];
    uint32_t h0 = packbf(v.x, v.y), h1 = packbf(v.z, v.w);
    uint32_t l0 = packbf_lo(v.x, v.y, h0), l1 = packbf_lo(v.z, v.w, h1);
    ((uint2*)hi)[i] = make_uint2(h0, h1);
    ((uint2*)lo)[i] = make_uint2(l0, l1);
}

__global__ void packT(const float* __restrict__ src, bf* __restrict__ hi, bf* __restrict__ lo, int R, int C){
    __shared__ float t[32][33];
    int c0 = blockIdx.x*32, r0 = blockIdx.y*32;
    for (int i = threadIdx.y; i < 32; i += 8)
        t[i][threadIdx.x] = src[(size_t)(r0+i)*C + c0 + threadIdx.x];
    __syncthreads();
    for (int i = threadIdx.y; i < 32; i += 8){
        float v = t[threadIdx.x][i];
        size_t o = (size_t)(c0+i)*R + r0 + threadIdx.x;
        bf h = __float2bfloat16(v);
        hi[o] = h; lo[o] = __float2bfloat16(v - __bfloat162float(h));
    }
}

// transpose dense v -> g_vt; zero tail (>= nvalid)
__global__ void vtrans_kernel(){
    __shared__ bf t[2][32][33];
    int z = blockIdx.z, b = z >> 3, h = z & 7;
    int j0 = blockIdx.x*32, d0 = blockIdx.y*32;
    int tx = threadIdx.x, ty = threadIdx.y;
    int nv = g_nvalid[b];
    #pragma unroll
    for (int s = 0; s < 2; s++)
        for (int i = ty; i < 32; i += 8){
            int jd = j0 + i;
            bf val = __float2bfloat16(0.f);
            if (jd < nv)
                val = g_vd[s][(size_t)(b*NKP + jd)*INNER + h*64 + d0 + tx];
            t[s][i][tx] = val;
        }
    __syncthreads();
    #pragma unroll
    for (int s = 0; s < 2; s++)
        for (int i = ty; i < 32; i += 8)
            g_vt[s][((size_t)z*DH + d0 + i)*NKP + j0 + tx] = t[s][tx][i];
}

// ---------------- fused flash attention (q-tile 128, fixed-shift softmax) ----------------
#define FSP 72
#define FTB (64*FSP*2)            // K/V tile: 9216 B
#define QTB (128*FSP*2)           // Q tile (128 rows): 18432 B
#define FSTG (4*FTB)              // stage: Kh,Kl,Vth,Vtl = 36864 B
#define FSMEM (2*QTB + 2*FSTG + 128)

__global__ __launch_bounds__(256, 1) void flash_kernel(){
    extern __shared__ __align__(16) char fsm[];
    const int tid = threadIdx.x, wid = tid >> 5, lane = tid & 31;
    const int z = blockIdx.y, b = z >> 3, h = z & 7;
    const int q0 = blockIdx.x*128;
    uint32_t sb = sm_u32(fsm);
    const uint32_t oQ = 0, oS = 2*QTB;

    const int nv = g_nvalid[b];
    const int ntiles = (nv + 63) >> 6;

    const bf* Qg[2] = { g_q[0] + ((size_t)(b*N + q0))*INNER + h*64,
                        g_q[1] + ((size_t)(b*N + q0))*INNER + h*64 };
    const bf* Kg[2] = { g_kd[0] + (size_t)b*NKP*INNER + h*64,
                        g_kd[1] + (size_t)b*NKP*INNER + h*64 };
    const bf* Vg[2] = { g_vt[0] + (size_t)z*DH*NKP,
                        g_vt[1] + (size_t)z*DH*NKP };

    auto load_stage = [&](int t){
        int j0 = t*64;
        uint32_t st = sb + oS + (t & 1)*FSTG;
        #pragma unroll 4
        for (int u = tid; u < 2048; u += 256){
            int tile = u >> 9, r = (u >> 3) & 63, sg = u & 7;
            const bf* src;
            if (tile == 0)      src = Kg[0] + (size_t)(j0 + r)*INNER + sg*8;
            else if (tile == 1) src = Kg[1] + (size_t)(j0 + r)*INNER + sg*8;
            else if (tile == 2) src = Vg[0] + (size_t)r*NKP + j0 + sg*8;
            else                src = Vg[1] + (size_t)r*NKP + j0 + sg*8;
            CP_ASYNC(st + tile*FTB + (uint32_t)(r*FSP + sg*8)*2, src);
        }
    };

    // Q prologue: 128 rows x 64 cols, hi + lo
    #pragma unroll 4
    for (int u = tid; u < 2048; u += 256){
        int half = u >> 10, r = (u >> 3) & 127, sg = u & 7;
        CP_ASYNC(sb + oQ + half*QTB + (uint32_t)(r*FSP + sg*8)*2,
                 Qg[half] + (size_t)r*INNER + sg*8);
    }
    if (ntiles > 0) load_stage(0);
    CP_COMMIT();
    if (ntiles > 1) load_stage(1);
    CP_COMMIT();

    uint32_t aQh[4][4], aQl[4][4];
    float lacc0 = 0.f, lacc1 = 0.f;
    float o[8][4];
    #pragma unroll
    for (int i = 0; i < 8; i++){ o[i][0]=0.f; o[i][1]=0.f; o[i][2]=0.f; o[i][3]=0.f; }

    const int gg = lane >> 3, ii = lane & 7, tq = lane & 3;

    for (int t = 0; t < ntiles; t++){
        if (t + 2 < ntiles) CP_WAIT1(); else CP_WAIT0();
        __syncthreads();

        if (t == 0){
            int row = wid*16 + (lane & 15);
            int col = (lane >> 4)*8;
            #pragma unroll
            for (int ks = 0; ks < 4; ks++){
                uint32_t ad = sb + oQ + (uint32_t)(row*FSP + ks*16 + col)*2;
                ldmx4(aQh[ks], ad);
                ldmx4(aQl[ks], ad + QTB);
            }
        }

        uint32_t st = sb + oS + (t & 1)*FSTG;

        float s[8][4];
        #pragma unroll
        for (int i = 0; i < 8; i++){ s[i][0]=0.f; s[i][1]=0.f; s[i][2]=0.f; s[i][3]=0.f; }
        #pragma unroll
        for (int ks = 0; ks < 4; ks++){
            #pragma unroll
            for (int p = 0; p < 4; p++){
                int rn = p*16 + (gg >> 1)*8 + ii;
                int ck = ks*16 + (gg & 1)*8;
                uint32_t off = (uint32_t)(rn*FSP + ck)*2;
                uint32_t bh[4], bl[4];
                ldmx4(bh, st + off);
                ldmx4(bl, st + FTB + off);
                mma16816(s[2*p],   aQh[ks], bh);
                mma16816(s[2*p],   aQh[ks], bl);
                mma16816(s[2*p],   aQl[ks], bh);
                mma16816(s[2*p+1], aQh[ks], bh + 2);
                mma16816(s[2*p+1], aQh[ks], bl + 2);
                mma16816(s[2*p+1], aQl[ks], bh + 2);
            }
        }

        int jb = t*64;
        #pragma unroll
        for (int nt = 0; nt < 8; nt++){
            int c0 = jb + nt*8 + tq*2;
            bool k0 = c0 < nv, k1 = (c0 + 1) < nv;
            s[nt][0] = fexp(k0 ? s[nt][0]*0.125f : -1e30f);
            s[nt][1] = fexp(k1 ? s[nt][1]*0.125f : -1e30f);
            s[nt][2] = fexp(k0 ? s[nt][2]*0.125f : -1e30f);
            s[nt][3] = fexp(k1 ? s[nt][3]*0.125f : -1e30f);
            lacc0 += s[nt][0] + s[nt][1];
            lacc1 += s[nt][2] + s[nt][3];
        }

        #pragma unroll
        for (int ks = 0; ks < 4; ks++){
            uint32_t aPh[4], aPl[4];
            aPh[0] = packbf(s[2*ks][0],   s[2*ks][1]);
            aPh[1] = packbf(s[2*ks][2],   s[2*ks][3]);
            aPh[2] = packbf(s[2*ks+1][0], s[2*ks+1][1]);
            aPh[3] = packbf(s[2*ks+1][2], s[2*ks+1][3]);
            aPl[0] = packbf_lo(s[2*ks][0],   s[2*ks][1],   aPh[0]);
            aPl[1] = packbf_lo(s[2*ks][2],   s[2*ks][3],   aPh[1]);
            aPl[2] = packbf_lo(s[2*ks+1][0], s[2*ks+1][1], aPh[2]);
            aPl[3] = packbf_lo(s[2*ks+1][2], s[2*ks+1][3], aPh[3]);
            #pragma unroll
            for (int dp = 0; dp < 4; dp++){
                int rn = dp*16 + (gg >> 1)*8 + ii;
                int ck = ks*16 + (gg & 1)*8;
                uint32_t off = (uint32_t)(rn*FSP + ck)*2;
                uint32_t vh[4], vl[4];
                ldmx4(vh, st + 2*FTB + off);
                ldmx4(vl, st + 3*FTB + off);
                mma16816(o[2*dp],   aPh, vh);
                mma16816(o[2*dp],   aPh, vl);
                mma16816(o[2*dp],   aPl, vh);
                mma16816(o[2*dp+1], aPh, vh + 2);
                mma16816(o[2*dp+1], aPh, vl + 2);
                mma16816(o[2*dp+1], aPl, vh + 2);
            }
        }
        __syncthreads();
        if (t + 2 < ntiles){ load_stage(t + 2); CP_COMMIT(); }
    }

    lacc0 += __shfl_xor_sync(~0u, lacc0, 1); lacc0 += __shfl_xor_sync(~0u, lacc0, 2);
    lacc1 += __shfl_xor_sync(~0u, lacc1, 1); lacc1 += __shfl_xor_sync(~0u, lacc1, 2);
    float inv0 = 1.0f / lacc0, inv1 = 1.0f / lacc1;

    int g = lane >> 2;
    int row0 = q0 + wid*16 + g, row1 = row0 + 8;
    ll base0 = ((ll)(b*N) + row0)*INNER + h*64;
    ll base1 = ((ll)(b*N) + row1)*INNER + h*64;
    #pragma unroll
    for (int nt = 0; nt < 8; nt++){
        int c = nt*8 + tq*2;
        float v0 = o[nt][0]*inv0, v1 = o[nt][1]*inv0;
        float v2 = o[nt][2]*inv1, v3 = o[nt][3]*inv1;
        uint32_t h0 = packbf(v0, v1), l0p = packbf_lo(v0, v1, h0);
        uint32_t h1 = packbf(v2, v3), l1p = packbf_lo(v2, v3, h1);
        *(uint32_t*)(g_ao[0] + base0 + c) = h0;
        *(uint32_t*)(g_ao[1] + base0 + c) = l0p;
        *(uint32_t*)(g_ao[0] + base1 + c) = h1;
        *(uint32_t*)(g_ao[1] + base1 + c) = l1p;
    }
}

// ---------------- warp-mma split-bf16 GEMM ----------------
// gathered==0: direct row addressing, output row = (row>>12)*remap + row&4095.
// gathered==1: grid.y = B*33 tiles over dense keys; A rows via g_gidx
//              (orig index N = bg key -> skip write), output dense at b*NKP + i.
struct GemmArgs {
    const bf *Ah, *Al, *Bh, *Bl;
    int K, lda, ldb;
    float* Cf; const float* bias;
    bf *Ch, *Cl;
    int ldc, remap, gathered;
};

template<int NTILE>
__global__ __launch_bounds__(256, 1) void gemm_mma(GemmArgs g){
    constexpr int KC = 32, KPAD = 40;
    constexpr int WGM = 2;
    constexpr int WM = 64;
    constexpr int WN = NTILE / 4;
    constexpr int MT = 4, NT = WN / 8;
    constexpr int ASZ = 128 * KPAD * 2;
    constexpr int BSZ = NTILE * KPAD * 2;
    constexpr int STAGE = 2*ASZ + 2*BSZ;
    constexpr int TOT = 1024 + NTILE*8;

    extern __shared__ __align__(16) char smem[];
    __shared__ ll rowoff[128];
    __shared__ int rowok[128];
    uint32_t sbase = sm_u32(smem);

    int tid = threadIdx.x, wid = tid >> 5, lane = tid & 31;
    int wm = wid % WGM, wn = wid / WGM;

    int bb = 0, m0 = 0;
    if (g.gathered){
        bb = blockIdx.y / 33;
        m0 = (blockIdx.y % 33) * 128;
        int nvv = g_nvalid[bb];
        if (m0 >= nvv) return;
        if (tid < 128){
            int i = m0 + tid;
            int src = (i < nvv) ? g_gidx[bb*NKP + i] : 0;
            int ok = (i < nvv) && (src != N);
            if (src >= N) src = 0;
            rowoff[tid] = ((ll)bb*N + src) * g.lda;
            rowok[tid] = ok;
        }
        __syncthreads();
    }

    const bf* pAh = g.Ah;
    const bf* pAl = g.Al;
    const bf* pBh = g.Bh + (ll)blockIdx.x*NTILE*g.ldb;
    const bf* pBl = g.Bl + (ll)blockIdx.x*NTILE*g.ldb;
    const ll arow0 = (ll)blockIdx.y*128;          // non-gathered base row

    float acc[MT][NT][4];
    #pragma unroll
    for (int i = 0; i < MT; i++)
        #pragma unroll
        for (int j = 0; j < NT; j++)
            #pragma unroll
            for (int e = 0; e < 4; e++) acc[i][j][e] = 0.f;

    int nch = g.K / KC;

    auto load_chunk = [&](int c){
        int s = c & 1, k0 = c * KC;
        uint32_t st = sbase + s*STAGE;
        if (g.gathered){
            #pragma unroll 2
            for (int u = tid; u < TOT; u += 256){
                const bf* src; uint32_t doff; int rel, isA;
                if (u < 512)              { rel = u;              src = pAh; doff = 0;         isA = 1; }
                else if (u < 1024)        { rel = u - 512;        src = pAl; doff = ASZ;       isA = 1; }
                else if (u < 1024+NTILE*4){ rel = u - 1024;       src = pBh; doff = 2*ASZ;     isA = 0; }
                else                      { rel = u-1024-NTILE*4; src = pBl; doff = 2*ASZ+BSZ; isA = 0; }
                int r = rel >> 2, sg = rel & 3;
                const bf* gs = isA ? (src + rowoff[r] + k0 + sg*8)
                                   : (src + (ll)r*g.ldb + k0 + sg*8);
                CP_ASYNC(st + doff + (uint32_t)(r*KPAD + sg*8)*2, gs);
            }
        } else {
            #pragma unroll 2
            for (int u = tid; u < TOT; u += 256){
                const bf* src; uint32_t doff; int rel, isA;
                if (u < 512)              { rel = u;              src = pAh; doff = 0;         isA = 1; }
                else if (u < 1024)        { rel = u - 512;        src = pAl; doff = ASZ;       isA = 1; }
                else if (u < 1024+NTILE*4){ rel = u - 1024;       src = pBh; doff = 2*ASZ;     isA = 0; }
                else                      { rel = u-1024-NTILE*4; src = pBl; doff = 2*ASZ+BSZ; isA = 0; }
                int r = rel >> 2, sg = rel & 3;
                const bf* gs = isA ? (src + (arow0 + r)*g.lda + k0 + sg*8)
                                   : (src + (ll)r*g.ldb + k0 + sg*8);
                CP_ASYNC(st + doff + (uint32_t)(r*KPAD + sg*8)*2, gs);
            }
        }
        CP_COMMIT();
    };

    load_chunk(0);
    for (int c = 0; c < nch; c++){
        if (c + 1 < nch){ load_chunk(c + 1); CP_WAIT1(); }
        else            { CP_WAIT0(); }
        __syncthreads();

        uint32_t stg = sbase + (c & 1)*STAGE;
        #pragma unroll
        for (int ks = 0; ks < 2; ks++){
            int kb = ks * 16;
            uint32_t aH[MT][4], aL[MT][4];
            #pragma unroll
            for (int mt = 0; mt < MT; mt++){
                int row = wm*WM + mt*16 + (lane & 15);
                int col = kb + (lane >> 4)*8;
                uint32_t ad = stg + (uint32_t)(row*KPAD + col)*2;
                ldmx4(aH[mt], ad);
                ldmx4(aL[mt], ad + ASZ);
            }
            #pragma unroll
            for (int p = 0; p < NT/2; p++){
                int gg = lane >> 3, ii = lane & 7;
                int row = wn*WN + p*16 + (gg >> 1)*8 + ii;
                int col = kb + (gg & 1)*8;
                uint32_t bd = stg + 2*ASZ + (uint32_t)(row*KPAD + col)*2;
                uint32_t bH[4], bL[4];
                ldmx4(bH, bd);
                ldmx4(bL, bd + BSZ);
                #pragma unroll
                for (int mt = 0; mt < MT; mt++){
                    mma16816(acc[mt][2*p],   aH[mt], bH);
                    mma16816(acc[mt][2*p],   aH[mt], bL);
                    mma16816(acc[mt][2*p],   aL[mt], bH);
                    mma16816(acc[mt][2*p+1], aH[mt], bH + 2);
                    mma16816(acc[mt][2*p+1], aH[mt], bL + 2);
                    mma16816(acc[mt][2*p+1], aL[mt], bH + 2);
                }
            }
        }
        __syncthreads();
    }

    int ncb = blockIdx.x*NTILE + wn*WN;
    #pragma unroll
    for (int mt = 0; mt < MT; mt++){
        #pragma unroll
        for (int hf = 0; hf < 2; hf++){
            int lrow = wm*WM + mt*16 + (lane >> 2) + hf*8;
            ll orow; bool wr = true;
            if (g.gathered){
                wr = rowok[lrow] != 0;
                orow = (ll)bb*NKP + m0 + lrow;
            } else {
                int row = blockIdx.y*128 + lrow;
                orow = (ll)(row >> 12)*g.remap + (row & 4095);
            }
            if (!wr) continue;
            ll basei = orow*(ll)g.ldc + ncb;
            #pragma unroll
            for (int nt = 0; nt < NT; nt++){
                int cl = nt*8 + (lane & 3)*2;
                float v0 = acc[mt][nt][hf*2], v1 = acc[mt][nt][hf*2+1];
                if (g.Cf){
                    if (g.bias){ v0 += g.bias[ncb + cl]; v1 += g.bias[ncb + cl + 1]; }
                    float2 f2; f2.x = v0; f2.y = v1;
                    *(float2*)(g.Cf + basei + cl) = f2;
                } else {
                    uint32_t hh = packbf(v0, v1);
                    uint32_t lo = packbf_lo(v0, v1, hh);
                    *(uint32_t*)(g.Ch + basei + cl) = hh;
                    *(uint32_t*)(g.Cl + basei + cl) = lo;
                }
            }
        }
    }
}

// ---------------- launch ----------------
extern "C" void kernel_launch(void* const* d_in, const int* in_sizes, int n_in,
                              void* d_out, int out_size){
    const float* x    = (const float*)d_in[0];
    const float* ctx  = (const float*)d_in[1];
    const unsigned char* mask = (const unsigned char*)d_in[2];
    const float* Wq   = (const float*)d_in[3];
    const float* Wk   = (const float*)d_in[4];
    const float* Wv   = (const float*)d_in[5];
    const float* Wkbg = (const float*)d_in[6];
    const float* Wvbg = (const float*)d_in[7];
    const float* Wout = (const float*)d_in[8];
    const float* bout = (const float*)d_in[9];
    float* out = (float*)d_out;

    bf *xs, *cs, *wq, *wk, *wv, *wo, *q, *kd, *vd, *ao;
    cudaGetSymbolAddress((void**)&xs, g_xs);
    cudaGetSymbolAddress((void**)&cs, g_cs);
    cudaGetSymbolAddress((void**)&wq, g_wq);
    cudaGetSymbolAddress((void**)&wk, g_wk);
    cudaGetSymbolAddress((void**)&wv, g_wv);
    cudaGetSymbolAddress((void**)&wo, g_wo);
    cudaGetSymbolAddress((void**)&q,  g_q);
    cudaGetSymbolAddress((void**)&kd, g_kd);
    cudaGetSymbolAddress((void**)&vd, g_vd);
    cudaGetSymbolAddress((void**)&ao, g_ao);
    const size_t XSZ = (size_t)B*N*QD, QSZ = (size_t)B*N*INNER;
    const size_t KSZ = (size_t)B*NKP*INNER;
    const size_t WSZ = (size_t)QD*INNER;

    const int SM128 = 2*(2*128*40*2 + 2*128*40*2);
    cudaFuncSetAttribute(gemm_mma<128>, cudaFuncAttributeMaxDynamicSharedMemorySize, SM128);
    cudaFuncSetAttribute(flash_kernel,  cudaFuncAttributeMaxDynamicSharedMemorySize, FSMEM);

    scan_kernel<<<B, 256>>>(mask);
    pooled_p1<<<dim3(B*QD/256, 16), 256>>>(x);
    pooled_p2<<<(B*QD + 255)/256, 256>>>();
    pack_split<<<(int)((XSZ/4 + 255)/256), 256>>>((const float4*)x,   xs, xs + XSZ, (int)(XSZ/4));
    pack_split<<<(int)((XSZ/4 + 255)/256), 256>>>((const float4*)ctx, cs, cs + XSZ, (int)(XSZ/4));
    packT<<<dim3(INNER/32, QD/32),    dim3(32, 8)>>>(Wq,   wq, wq + WSZ, QD, INNER);
    packT<<<dim3(INNER/32, QD/32),    dim3(32, 8)>>>(Wk,   wk, wk + WSZ, CD, INNER);
    packT<<<dim3(INNER/32, QD/32),    dim3(32, 8)>>>(Wv,   wv, wv + WSZ, CD, INNER);
    packT<<<dim3(QD/32,    INNER/32), dim3(32, 8)>>>(Wout, wo, wo + WSZ, INNER, QD);
    bg_kernel<<<(B*INNER + 255)/256, 256>>>(Wkbg, Wvbg);

    GemmArgs a;
    // q = x @ Wq (full)
    a = { xs, xs + XSZ, wq, wq + WSZ, QD, QD, QD,
          nullptr, nullptr, q, q + QSZ, INNER, 4096, 0 };
    gemm_mma<128><<<dim3(INNER/128, (B*N)/128, 1), 256, SM128>>>(a);
    // k = gather(ctx) @ Wk  (dense keys only)
    a = { cs, cs + XSZ, wk, wk + WSZ, CD, CD, CD,
          nullptr, nullptr, kd, kd + KSZ, INNER, NKP, 1 };
    gemm_mma<128><<<dim3(INNER/128, B*33, 1), 256, SM128>>>(a);
    // v = gather(ctx) @ Wv  (dense keys only)
    a = { cs, cs + XSZ, wv, wv + WSZ, CD, CD, CD,
          nullptr, nullptr, vd, vd + KSZ, INNER, NKP, 1 };
    gemm_mma<128><<<dim3(INNER/128, B*33, 1), 256, SM128>>>(a);
    // vT (transpose dense, zero tail)
    vtrans_kernel<<<dim3(NKP/32, DH/32, B*H), dim3(32, 8)>>>();
    // fused attention over dense keys (q-tile 128)
    flash_kernel<<<dim3(N/128, B*H), 256, FSMEM>>>();
    // out = ao @ Wout + b
    a = { ao, ao + QSZ, wo, wo + WSZ, INNER, INNER, INNER,
          out, bout, nullptr, nullptr, QD, 4096, 0 };
    gemm_mma<128><<<dim3(QD/128, (B*N)/128, 1), 256, SM128>>>(a);
}

// round 10
// speedup vs baseline: 1.4547x; 1.4547x over previous
#include <cuda_runtime.h>
#include <cuda_bf16.h>
#include <cstdint>

#define B     2
#define N     4096
#define QD    1024
#define CD    1024
#define H     8
#define DH    64
#define INNER 512
#define NK    4097
#define NKP   4224
typedef long long ll;
typedef __nv_bfloat16 bf;

// ---------------- device scratch ----------------
__device__ __align__(16) bf g_xs[2][B*N*QD];
__device__ __align__(16) bf g_cs[2][B*N*CD];
__device__ __align__(16) bf g_wq[2][QD*INNER];
__device__ __align__(16) bf g_wk[2][CD*INNER];
__device__ __align__(16) bf g_wv[2][CD*INNER];
__device__ __align__(16) bf g_wo[2][INNER*QD];
__device__ __align__(16) bf g_q [2][B*N*INNER];
__device__ __align__(16) bf g_vd[2][B*NKP*INNER];    // dense v
__device__ __align__(16) bf g_kd[2][B*NKP*INNER];    // dense k
__device__ __align__(16) bf g_vt[2][B*H*DH*NKP];     // dense v, transposed
__device__ __align__(16) bf g_ao[2][B*N*INNER];
__device__ float g_ppart[16][B*QD];
__device__ float g_pooled[B*QD];
__device__ int g_gidx[B*NKP];     // dense -> orig
__device__ int g_scat[B*NKP];     // orig -> dense (or -1)
__device__ int g_nvalid[B];

// ---------------- helpers ----------------
__device__ __forceinline__ uint32_t sm_u32(const void* p){
    uint32_t a;
    asm("{ .reg .u64 t; cvta.to.shared.u64 t, %1; cvt.u32.u64 %0, t; }" : "=r"(a) : "l"(p));
    return a;
}
__device__ __forceinline__ void ldmx4(uint32_t* r, uint32_t addr){
    asm volatile("ldmatrix.sync.aligned.m8n8.x4.shared.b16 {%0,%1,%2,%3}, [%4];"
        : "=r"(r[0]), "=r"(r[1]), "=r"(r[2]), "=r"(r[3]) : "r"(addr));
}
__device__ __forceinline__ void mma16816(float* d, const uint32_t* a, const uint32_t* b){
    asm volatile("mma.sync.aligned.m16n8k16.row.col.f32.bf16.bf16.f32 "
        "{%0,%1,%2,%3}, {%4,%5,%6,%7}, {%8,%9}, {%0,%1,%2,%3};"
        : "+f"(d[0]), "+f"(d[1]), "+f"(d[2]), "+f"(d[3])
        : "r"(a[0]), "r"(a[1]), "r"(a[2]), "r"(a[3]), "r"(b[0]), "r"(b[1]));
}
#define CP_ASYNC(dst, src) \
    asm volatile("cp.async.cg.shared.global [%0], [%1], 16;" :: "r"(dst), "l"(src))
#define CP_COMMIT() asm volatile("cp.async.commit_group;" ::: "memory")
#define CP_WAIT1()  asm volatile("cp.async.wait_group 1;" ::: "memory")
#define CP_WAIT0()  asm volatile("cp.async.wait_group 0;" ::: "memory")

__device__ __forceinline__ uint32_t packbf(float a, float b){
    uint32_t r;
    asm("cvt.rn.bf16x2.f32 %0, %1, %2;" : "=r"(r) : "f"(b), "f"(a));
    return r;
}
__device__ __forceinline__ uint32_t packbf_lo(float a, float b, uint32_t hi){
    float hx = __uint_as_float((hi & 0xFFFFu) << 16);
    float hy = __uint_as_float(hi & 0xFFFF0000u);
    return packbf(a - hx, b - hy);
}
__device__ __forceinline__ float fexp(float x){
    float t = fmaxf(x * 1.4426950409f, -120.f);
    float r = rintf(t);
    float f = t - r;
    float p = 1.33336e-3f;
    p = fmaf(p, f, 9.61812e-3f);
    p = fmaf(p, f, 5.55041e-2f);
    p = fmaf(p, f, 2.4022651e-1f);
    p = fmaf(p, f, 6.9314718e-1f);
    p = fmaf(p, f, 1.0f);
    return p * __int_as_float(((int)r + 127) << 23);
}

// ---------------- mask scan ----------------
__global__ void scan_kernel(const unsigned char* __restrict__ m){
    __shared__ int anynz;
    __shared__ int sc[256];
    int tid = threadIdx.x, b = blockIdx.x;
    if (tid == 0) anynz = 0;
    __syncthreads();
    int loc = 0;
    for (int i = tid; i < 8192; i += 256)
        if ((i & 3) && m[i]) loc = 1;
    if (loc) atomicOr(&anynz, 1);
    __syncthreads();
    bool u8 = (anynz != 0);
    const int* mi = (const int*)m;

    int base = tid * 17, c = 0;
    unsigned int bits = 0;
    #pragma unroll
    for (int e = 0; e < 17; e++){
        int w = base + e;
        int on = 0;
        if (w < NK) on = u8 ? (m[b*NK + w] != 0) : (mi[b*NK + w] != 0);
        bits |= (unsigned)on << e;
        c += on;
    }
    sc[tid] = c;
    __syncthreads();
    for (int off = 1; off < 256; off <<= 1){
        int v = (tid >= off) ? sc[tid - off] : 0;
        __syncthreads();
        sc[tid] += v;
        __syncthreads();
    }
    int pos = sc[tid] - c;
    #pragma unroll
    for (int e = 0; e < 17; e++){
        int w = base + e;
        if (w < NKP){
            if ((bits >> e) & 1){
                g_gidx[b*NKP + pos] = w;
                g_scat[b*NKP + w] = pos;
                pos++;
            } else {
                g_scat[b*NKP + w] = -1;
            }
        }
    }
    __syncthreads();
    int nvv = sc[255];
    if (tid == 0) g_nvalid[b] = nvv;
    for (int i = nvv + tid; i < NKP; i += 256) g_gidx[b*NKP + i] = 0;
}

// ---------------- pooled mean ----------------
__global__ void pooled_p1(const float* __restrict__ x){
    int id = blockIdx.x*256 + threadIdx.x;
    int chunk = blockIdx.y;
    int b = id / QD, d = id % QD;
    const float* p = x + (size_t)b*N*QD + (size_t)chunk*256*QD + d;
    float s = 0.f;
    #pragma unroll 8
    for (int n = 0; n < 256; n++) s += p[(size_t)n*QD];
    g_ppart[chunk][id] = s;
}
__global__ void pooled_p2(){
    int id = blockIdx.x*256 + threadIdx.x;
    if (id >= B*QD) return;
    float s = 0.f;
    #pragma unroll
    for (int c = 0; c < 16; c++) s += g_ppart[c][id];
    g_pooled[id] = s * (1.0f/N);
}

__global__ void bg_kernel(const float* __restrict__ Wkbg, const float* __restrict__ Wvbg){
    int id = blockIdx.x*256 + threadIdx.x;
    if (id >= B*INNER) return;
    int b = id / INNER, o = id % INNER;
    int pos = g_scat[b*NKP + N];
    if (pos < 0) return;
    float sk = 0.f, sv = 0.f;
    for (int k = 0; k < QD; k++){
        float pv = g_pooled[b*QD + k];
        sk += pv * Wkbg[(size_t)k*INNER + o];
        sv += pv * Wvbg[(size_t)k*INNER + o];
    }
    size_t kb = (size_t)(b*NKP + pos)*INNER + o;
    bf h;
    h = __float2bfloat16(sk); g_kd[0][kb] = h; g_kd[1][kb] = __float2bfloat16(sk - __bfloat162float(h));
    h = __float2bfloat16(sv); g_vd[0][kb] = h; g_vd[1][kb] = __float2bfloat16(sv - __bfloat162float(h));
}

__global__ void pack_split(const float4* __restrict__ src, bf* __restrict__ hi, bf* __restrict__ lo, int n4){
    int i = blockIdx.x*256 + threadIdx.x;
    if (i >= n4) return;
    float4 v = src[i];
    uint32_t h0 = packbf(v.x, v.y), h1 = packbf(v.z, v.w);
    uint32_t l0 = packbf_lo(v.x, v.y, h0), l1 = packbf_lo(v.z, v.w, h1);
    ((uint2*)hi)[i] = make_uint2(h0, h1);
    ((uint2*)lo)[i] = make_uint2(l0, l1);
}

__global__ void packT(const float* __restrict__ src, bf* __restrict__ hi, bf* __restrict__ lo, int R, int C){
    __shared__ float t[32][33];
    int c0 = blockIdx.x*32, r0 = blockIdx.y*32;
    for (int i = threadIdx.y; i < 32; i += 8)
        t[i][threadIdx.x] = src[(size_t)(r0+i)*C + c0 + threadIdx.x];
    __syncthreads();
    for (int i = threadIdx.y; i < 32; i += 8){
        float v = t[threadIdx.x][i];
        size_t o = (size_t)(c0+i)*R + r0 + threadIdx.x;
        bf h = __float2bfloat16(v);
        hi[o] = h; lo[o] = __float2bfloat16(v - __bfloat162float(h));
    }
}

// transpose dense v -> g_vt; zero tail (>= nvalid)
__global__ void vtrans_kernel(){
    __shared__ bf t[2][32][33];
    int z = blockIdx.z, b = z >> 3, h = z & 7;
    int j0 = blockIdx.x*32, d0 = blockIdx.y*32;
    int tx = threadIdx.x, ty = threadIdx.y;
    int nv = g_nvalid[b];
    #pragma unroll
    for (int s = 0; s < 2; s++)
        for (int i = ty; i < 32; i += 8){
            int jd = j0 + i;
            bf val = __float2bfloat16(0.f);
            if (jd < nv)
                val = g_vd[s][(size_t)(b*NKP + jd)*INNER + h*64 + d0 + tx];
            t[s][i][tx] = val;
        }
    __syncthreads();
    #pragma unroll
    for (int s = 0; s < 2; s++)
        for (int i = ty; i < 32; i += 8)
            g_vt[s][((size_t)z*DH + d0 + i)*NKP + j0 + tx] = t[s][tx][i];
}

// ---------------- fused flash attention (64-q tile, 2 CTAs/SM) ----------------
#define FSP 72
#define FTB (64*FSP*2)
#define FSTG (4*FTB)
#define FSMEM (2*FTB + 2*FSTG + 128)

__global__ __launch_bounds__(128, 2) void flash_kernel(){
    extern __shared__ __align__(16) char fsm[];
    const int tid = threadIdx.x, wid = tid >> 5, lane = tid & 31;
    const int z = blockIdx.y, b = z >> 3, h = z & 7;
    const int q0 = blockIdx.x*64;
    uint32_t sb = sm_u32(fsm);
    const uint32_t oQ = 0, oS = 2*FTB;

    const int nv = g_nvalid[b];
    const int ntiles = (nv + 63) >> 6;

    const bf* Qg[2] = { g_q[0] + ((size_t)(b*N + q0))*INNER + h*64,
                        g_q[1] + ((size_t)(b*N + q0))*INNER + h*64 };
    const bf* Kg[2] = { g_kd[0] + (size_t)b*NKP*INNER + h*64,
                        g_kd[1] + (size_t)b*NKP*INNER + h*64 };
    const bf* Vg[2] = { g_vt[0] + (size_t)z*DH*NKP,
                        g_vt[1] + (size_t)z*DH*NKP };

    auto load_stage = [&](int t){
        int j0 = t*64;
        uint32_t st = sb + oS + (t & 1)*FSTG;
        #pragma unroll 4
        for (int u = tid; u < 2048; u += 128){
            int tile = u >> 9, r = (u >> 3) & 63, sg = u & 7;
            const bf* src;
            if (tile == 0)      src = Kg[0] + (size_t)(j0 + r)*INNER + sg*8;
            else if (tile == 1) src = Kg[1] + (size_t)(j0 + r)*INNER + sg*8;
            else if (tile == 2) src = Vg[0] + (size_t)r*NKP + j0 + sg*8;
            else                src = Vg[1] + (size_t)r*NKP + j0 + sg*8;
            CP_ASYNC(st + tile*FTB + (uint32_t)(r*FSP + sg*8)*2, src);
        }
    };

    #pragma unroll 4
    for (int u = tid; u < 1024; u += 128){
        int half = u >> 9, r = (u >> 3) & 63, sg = u & 7;
        CP_ASYNC(sb + oQ + half*FTB + (uint32_t)(r*FSP + sg*8)*2,
                 Qg[half] + (size_t)r*INNER + sg*8);
    }
    if (ntiles > 0) load_stage(0);
    CP_COMMIT();
    if (ntiles > 1) load_stage(1);
    CP_COMMIT();

    uint32_t aQh[4][4], aQl[4][4];
    float lacc0 = 0.f, lacc1 = 0.f;
    float o[8][4];
    #pragma unroll
    for (int i = 0; i < 8; i++){ o[i][0]=0.f; o[i][1]=0.f; o[i][2]=0.f; o[i][3]=0.f; }

    const int gg = lane >> 3, ii = lane & 7, tq = lane & 3;

    for (int t = 0; t < ntiles; t++){
        if (t + 2 < ntiles) CP_WAIT1(); else CP_WAIT0();
        __syncthreads();

        if (t == 0){
            int row = wid*16 + (lane & 15);
            int col = (lane >> 4)*8;
            #pragma unroll
            for (int ks = 0; ks < 4; ks++){
                uint32_t ad = sb + oQ + (uint32_t)(row*FSP + ks*16 + col)*2;
                ldmx4(aQh[ks], ad);
                ldmx4(aQl[ks], ad + FTB);
            }
        }

        uint32_t st = sb + oS + (t & 1)*FSTG;

        float s[8][4];
        #pragma unroll
        for (int i = 0; i < 8; i++){ s[i][0]=0.f; s[i][1]=0.f; s[i][2]=0.f; s[i][3]=0.f; }
        #pragma unroll
        for (int ks = 0; ks < 4; ks++){
            #pragma unroll
            for (int p = 0; p < 4; p++){
                int rn = p*16 + (gg >> 1)*8 + ii;
                int ck = ks*16 + (gg & 1)*8;
                uint32_t off = (uint32_t)(rn*FSP + ck)*2;
                uint32_t bh[4], bl[4];
                ldmx4(bh, st + off);
                ldmx4(bl, st + FTB + off);
                mma16816(s[2*p],   aQh[ks], bh);
                mma16816(s[2*p],   aQh[ks], bl);
                mma16816(s[2*p],   aQl[ks], bh);
                mma16816(s[2*p+1], aQh[ks], bh + 2);
                mma16816(s[2*p+1], aQh[ks], bl + 2);
                mma16816(s[2*p+1], aQl[ks], bh + 2);
            }
        }

        int jb = t*64;
        #pragma unroll
        for (int nt = 0; nt < 8; nt++){
            int c0 = jb + nt*8 + tq*2;
            bool k0 = c0 < nv, k1 = (c0 + 1) < nv;
            s[nt][0] = fexp(k0 ? s[nt][0]*0.125f : -1e30f);
            s[nt][1] = fexp(k1 ? s[nt][1]*0.125f : -1e30f);
            s[nt][2] = fexp(k0 ? s[nt][2]*0.125f : -1e30f);
            s[nt][3] = fexp(k1 ? s[nt][3]*0.125f : -1e30f);
            lacc0 += s[nt][0] + s[nt][1];
            lacc1 += s[nt][2] + s[nt][3];
        }

        #pragma unroll
        for (int ks = 0; ks < 4; ks++){
            uint32_t aPh[4], aPl[4];
            aPh[0] = packbf(s[2*ks][0],   s[2*ks][1]);
            aPh[1] = packbf(s[2*ks][2],   s[2*ks][3]);
            aPh[2] = packbf(s[2*ks+1][0], s[2*ks+1][1]);
            aPh[3] = packbf(s[2*ks+1][2], s[2*ks+1][3]);
            aPl[0] = packbf_lo(s[2*ks][0],   s[2*ks][1],   aPh[0]);
            aPl[1] = packbf_lo(s[2*ks][2],   s[2*ks][3],   aPh[1]);
            aPl[2] = packbf_lo(s[2*ks+1][0], s[2*ks+1][1], aPh[2]);
            aPl[3] = packbf_lo(s[2*ks+1][2], s[2*ks+1][3], aPh[3]);
            #pragma unroll
            for (int dp = 0; dp < 4; dp++){
                int rn = dp*16 + (gg >> 1)*8 + ii;
                int ck = ks*16 + (gg & 1)*8;
                uint32_t off = (uint32_t)(rn*FSP + ck)*2;
                uint32_t vh[4], vl[4];
                ldmx4(vh, st + 2*FTB + off);
                ldmx4(vl, st + 3*FTB + off);
                mma16816(o[2*dp],   aPh, vh);
                mma16816(o[2*dp],   aPh, vl);
                mma16816(o[2*dp],   aPl, vh);
                mma16816(o[2*dp+1], aPh, vh + 2);
                mma16816(o[2*dp+1], aPh, vl + 2);
                mma16816(o[2*dp+1], aPl, vh + 2);
            }
        }
        __syncthreads();
        if (t + 2 < ntiles){ load_stage(t + 2); CP_COMMIT(); }
    }

    lacc0 += __shfl_xor_sync(~0u, lacc0, 1); lacc0 += __shfl_xor_sync(~0u, lacc0, 2);
    lacc1 += __shfl_xor_sync(~0u, lacc1, 1); lacc1 += __shfl_xor_sync(~0u, lacc1, 2);
    float inv0 = 1.0f / lacc0, inv1 = 1.0f / lacc1;

    int g = lane >> 2;
    int row0 = q0 + wid*16 + g, row1 = row0 + 8;
    ll base0 = ((ll)(b*N) + row0)*INNER + h*64;
    ll base1 = ((ll)(b*N) + row1)*INNER + h*64;
    #pragma unroll
    for (int nt = 0; nt < 8; nt++){
        int c = nt*8 + tq*2;
        float v0 = o[nt][0]*inv0, v1 = o[nt][1]*inv0;
        float v2 = o[nt][2]*inv1, v3 = o[nt][3]*inv1;
        uint32_t h0 = packbf(v0, v1), l0p = packbf_lo(v0, v1, h0);
        uint32_t h1 = packbf(v2, v3), l1p = packbf_lo(v2, v3, h1);
        *(uint32_t*)(g_ao[0] + base0 + c) = h0;
        *(uint32_t*)(g_ao[1] + base0 + c) = l0p;
        *(uint32_t*)(g_ao[0] + base1 + c) = h1;
        *(uint32_t*)(g_ao[1] + base1 + c) = l1p;
    }
}

// ---------------- warp-mma split-bf16 GEMM ----------------
struct GemmArgs {
    const bf *Ah, *Al, *Bh, *Bl;
    int K, lda, ldb;
    float* Cf; const float* bias;
    bf *Ch, *Cl;
    int ldc, remap, gathered;
};

template<int NTILE>
__global__ __launch_bounds__(256, 1) void gemm_mma(GemmArgs g){
    constexpr int KC = 32, KPAD = 40;
    constexpr int WGM = 2;
    constexpr int WM = 64;
    constexpr int WN = NTILE / 4;
    constexpr int MT = 4, NT = WN / 8;
    constexpr int ASZ = 128 * KPAD * 2;
    constexpr int BSZ = NTILE * KPAD * 2;
    constexpr int STAGE = 2*ASZ + 2*BSZ;
    constexpr int TOT = 1024 + NTILE*8;

    extern __shared__ __align__(16) char smem[];
    __shared__ ll rowoff[128];
    __shared__ int rowok[128];
    uint32_t sbase = sm_u32(smem);

    int tid = threadIdx.x, wid = tid >> 5, lane = tid & 31;
    int wm = wid % WGM, wn = wid / WGM;

    int bb = 0, m0 = 0;
    if (g.gathered){
        bb = blockIdx.y / 33;
        m0 = (blockIdx.y % 33) * 128;
        int nvv = g_nvalid[bb];
        if (m0 >= nvv) return;
        if (tid < 128){
            int i = m0 + tid;
            int src = (i < nvv) ? g_gidx[bb*NKP + i] : 0;
            int ok = (i < nvv) && (src != N);
            if (src >= N) src = 0;
            rowoff[tid] = ((ll)bb*N + src) * g.lda;
            rowok[tid] = ok;
        }
        __syncthreads();
    }

    const bf* pAh = g.Ah;
    const bf* pAl = g.Al;
    const bf* pBh = g.Bh + (ll)blockIdx.x*NTILE*g.ldb;
    const bf* pBl = g.Bl + (ll)blockIdx.x*NTILE*g.ldb;
    const ll arow0 = (ll)blockIdx.y*128;

    float acc[MT][NT][4];
    #pragma unroll
    for (int i = 0; i < MT; i++)
        #pragma unroll
        for (int j = 0; j < NT; j++)
            #pragma unroll
            for (int e = 0; e < 4; e++) acc[i][j][e] = 0.f;

    int nch = g.K / KC;

    auto load_chunk = [&](int c){
        int s = c & 1, k0 = c * KC;
        uint32_t st = sbase + s*STAGE;
        if (g.gathered){
            #pragma unroll 2
            for (int u = tid; u < TOT; u += 256){
                const bf* src; uint32_t doff; int rel, isA;
                if (u < 512)              { rel = u;              src = pAh; doff = 0;         isA = 1; }
                else if (u < 1024)        { rel = u - 512;        src = pAl; doff = ASZ;       isA = 1; }
                else if (u < 1024+NTILE*4){ rel = u - 1024;       src = pBh; doff = 2*ASZ;     isA = 0; }
                else                      { rel = u-1024-NTILE*4; src = pBl; doff = 2*ASZ+BSZ; isA = 0; }
                int r = rel >> 2, sg = rel & 3;
                const bf* gs = isA ? (src + rowoff[r] + k0 + sg*8)
                                   : (src + (ll)r*g.ldb + k0 + sg*8);
                CP_ASYNC(st + doff + (uint32_t)(r*KPAD + sg*8)*2, gs);
            }
        } else {
            #pragma unroll 2
            for (int u = tid; u < TOT; u += 256){
                const bf* src; uint32_t doff; int rel, isA;
                if (u < 512)              { rel = u;              src = pAh; doff = 0;         isA = 1; }
                else if (u < 1024)        { rel = u - 512;        src = pAl; doff = ASZ;       isA = 1; }
                else if (u < 1024+NTILE*4){ rel = u - 1024;       src = pBh; doff = 2*ASZ;     isA = 0; }
                else                      { rel = u-1024-NTILE*4; src = pBl; doff = 2*ASZ+BSZ; isA = 0; }
                int r = rel >> 2, sg = rel & 3;
                const bf* gs = isA ? (src + (arow0 + r)*g.lda + k0 + sg*8)
                                   : (src + (ll)r*g.ldb + k0 + sg*8);
                CP_ASYNC(st + doff + (uint32_t)(r*KPAD + sg*8)*2, gs);
            }
        }
        CP_COMMIT();
    };

    load_chunk(0);
    for (int c = 0; c < nch; c++){
        if (c + 1 < nch){ load_chunk(c + 1); CP_WAIT1(); }
        else            { CP_WAIT0(); }
        __syncthreads();

        uint32_t stg = sbase + (c & 1)*STAGE;
        #pragma unroll
        for (int ks = 0; ks < 2; ks++){
            int kb = ks * 16;
            uint32_t aH[MT][4], aL[MT][4];
            #pragma unroll
            for (int mt = 0; mt < MT; mt++){
                int row = wm*WM + mt*16 + (lane & 15);
                int col = kb + (lane >> 4)*8;
                uint32_t ad = stg + (uint32_t)(row*KPAD + col)*2;
                ldmx4(aH[mt], ad);
                ldmx4(aL[mt], ad + ASZ);
            }
            #pragma unroll
            for (int p = 0; p < NT/2; p++){
                int gg = lane >> 3, ii = lane & 7;
                int row = wn*WN + p*16 + (gg >> 1)*8 + ii;
                int col = kb + (gg & 1)*8;
                uint32_t bd = stg + 2*ASZ + (uint32_t)(row*KPAD + col)*2;
                uint32_t bH[4], bL[4];
                ldmx4(bH, bd);
                ldmx4(bL, bd + BSZ);
                #pragma unroll
                for (int mt = 0; mt < MT; mt++){
                    mma16816(acc[mt][2*p],   aH[mt], bH);
                    mma16816(acc[mt][2*p],   aH[mt], bL);
                    mma16816(acc[mt][2*p],   aL[mt], bH);
                    mma16816(acc[mt][2*p+1], aH[mt], bH + 2);
                    mma16816(acc[mt][2*p+1], aH[mt], bL + 2);
                    mma16816(acc[mt][2*p+1], aL[mt], bH + 2);
                }
            }
        }
        __syncthreads();
    }

    int ncb = blockIdx.x*NTILE + wn*WN;
    #pragma unroll
    for (int mt = 0; mt < MT; mt++){
        #pragma unroll
        for (int hf = 0; hf < 2; hf++){
            int lrow = wm*WM + mt*16 + (lane >> 2) + hf*8;
            ll orow; bool wr = true;
            if (g.gathered){
                wr = rowok[lrow] != 0;
                orow = (ll)bb*NKP + m0 + lrow;
            } else {
                int row = blockIdx.y*128 + lrow;
                orow = (ll)(row >> 12)*g.remap + (row & 4095);
            }
            if (!wr) continue;
            ll basei = orow*(ll)g.ldc + ncb;
            #pragma unroll
            for (int nt = 0; nt < NT; nt++){
                int cl = nt*8 + (lane & 3)*2;
                float v0 = acc[mt][nt][hf*2], v1 = acc[mt][nt][hf*2+1];
                if (g.Cf){
                    if (g.bias){ v0 += g.bias[ncb + cl]; v1 += g.bias[ncb + cl + 1]; }
                    float2 f2; f2.x = v0; f2.y = v1;
                    *(float2*)(g.Cf + basei + cl) = f2;
                } else {
                    uint32_t hh = packbf(v0, v1);
                    uint32_t lo = packbf_lo(v0, v1, hh);
                    *(uint32_t*)(g.Ch + basei + cl) = hh;
                    *(uint32_t*)(g.Cl + basei + cl) = lo;
                }
            }
        }
    }
}

// ---------------- launch ----------------
extern "C" void kernel_launch(void* const* d_in, const int* in_sizes, int n_in,
                              void* d_out, int out_size){
    const float* x    = (const float*)d_in[0];
    const float* ctx  = (const float*)d_in[1];
    const unsigned char* mask = (const unsigned char*)d_in[2];
    const float* Wq   = (const float*)d_in[3];
    const float* Wk   = (const float*)d_in[4];
    const float* Wv   = (const float*)d_in[5];
    const float* Wkbg = (const float*)d_in[6];
    const float* Wvbg = (const float*)d_in[7];
    const float* Wout = (const float*)d_in[8];
    const float* bout = (const float*)d_in[9];
    float* out = (float*)d_out;

    bf *xs, *cs, *wq, *wk, *wv, *wo, *q, *kd, *vd, *ao;
    cudaGetSymbolAddress((void**)&xs, g_xs);
    cudaGetSymbolAddress((void**)&cs, g_cs);
    cudaGetSymbolAddress((void**)&wq, g_wq);
    cudaGetSymbolAddress((void**)&wk, g_wk);
    cudaGetSymbolAddress((void**)&wv, g_wv);
    cudaGetSymbolAddress((void**)&wo, g_wo);
    cudaGetSymbolAddress((void**)&q,  g_q);
    cudaGetSymbolAddress((void**)&kd, g_kd);
    cudaGetSymbolAddress((void**)&vd, g_vd);
    cudaGetSymbolAddress((void**)&ao, g_ao);
    const size_t XSZ = (size_t)B*N*QD, QSZ = (size_t)B*N*INNER;
    const size_t KSZ = (size_t)B*NKP*INNER;
    const size_t WSZ = (size_t)QD*INNER;

    const int SM128 = 2*(2*128*40*2 + 2*128*40*2);
    cudaFuncSetAttribute(gemm_mma<128>, cudaFuncAttributeMaxDynamicSharedMemorySize, SM128);
    cudaFuncSetAttribute(flash_kernel,  cudaFuncAttributeMaxDynamicSharedMemorySize, FSMEM);

    scan_kernel<<<B, 256>>>(mask);
    pooled_p1<<<dim3(B*QD/256, 16), 256>>>(x);
    pooled_p2<<<(B*QD + 255)/256, 256>>>();
    pack_split<<<(int)((XSZ/4 + 255)/256), 256>>>((const float4*)x,   xs, xs + XSZ, (int)(XSZ/4));
    pack_split<<<(int)((XSZ/4 + 255)/256), 256>>>((const float4*)ctx, cs, cs + XSZ, (int)(XSZ/4));
    packT<<<dim3(INNER/32, QD/32),    dim3(32, 8)>>>(Wq,   wq, wq + WSZ, QD, INNER);
    packT<<<dim3(INNER/32, QD/32),    dim3(32, 8)>>>(Wk,   wk, wk + WSZ, CD, INNER);
    packT<<<dim3(INNER/32, QD/32),    dim3(32, 8)>>>(Wv,   wv, wv + WSZ, CD, INNER);
    packT<<<dim3(QD/32,    INNER/32), dim3(32, 8)>>>(Wout, wo, wo + WSZ, INNER, QD);
    bg_kernel<<<(B*INNER + 255)/256, 256>>>(Wkbg, Wvbg);

    GemmArgs a;
    // q = x @ Wq (full, direct addressing)
    a = { xs, xs + XSZ, wq, wq + WSZ, QD, QD, QD,
          nullptr, nullptr, q, q + QSZ, INNER, 4096, 0 };
    gemm_mma<128><<<dim3(INNER/128, (B*N)/128, 1), 256, SM128>>>(a);
    // k = gather(ctx) @ Wk  (dense keys only)
    a = { cs, cs + XSZ, wk, wk + WSZ, CD, CD, CD,
          nullptr, nullptr, kd, kd + KSZ, INNER, NKP, 1 };
    gemm_mma<128><<<dim3(INNER/128, B*33, 1), 256, SM128>>>(a);
    // v = gather(ctx) @ Wv  (dense keys only)
    a = { cs, cs + XSZ, wv, wv + WSZ, CD, CD, CD,
          nullptr, nullptr, vd, vd + KSZ, INNER, NKP, 1 };
    gemm_mma<128><<<dim3(INNER/128, B*33, 1), 256, SM128>>>(a);
    // vT (transpose dense, zero tail)
    vtrans_kernel<<<dim3(NKP/32, DH/32, B*H), dim3(32, 8)>>>();
    // fused attention (64-q tiles, 2 CTAs/SM)
    flash_kernel<<<dim3(N/64, B*H), 128, FSMEM>>>();
    // out = ao @ Wout + b
    a = { ao, ao + QSZ, wo, wo + WSZ, INNER, INNER, INNER,
          out, bout, nullptr, nullptr, QD, 4096, 0 };
    gemm_mma<128><<<dim3(QD/128, (B*N)/128, 1), 256, SM128>>>(a);
}

// round 11
// speedup vs baseline: 1.4664x; 1.0081x over previous
#include <cuda_runtime.h>
#include <cuda_bf16.h>
#include <cstdint>

#define B     2
#define N     4096
#define QD    1024
#define CD    1024
#define H     8
#define DH    64
#define INNER 512
#define NK    4097
#define NKP   4224
typedef long long ll;
typedef __nv_bfloat16 bf;

// ---------------- device scratch ----------------
__device__ __align__(16) bf g_xs[2][B*N*QD];
__device__ __align__(16) bf g_cs[2][B*N*CD];
__device__ __align__(16) bf g_wq[2][QD*INNER];
__device__ __align__(16) bf g_wk[2][CD*INNER];
__device__ __align__(16) bf g_wv[2][CD*INNER];
__device__ __align__(16) bf g_wo[2][INNER*QD];
__device__ __align__(16) bf g_q [2][B*N*INNER];
__device__ __align__(16) bf g_vd[2][B*NKP*INNER];    // dense v
__device__ __align__(16) bf g_kd[2][B*NKP*INNER];    // dense k
__device__ __align__(16) bf g_vt[2][B*H*DH*NKP];     // dense v, transposed
__device__ __align__(16) bf g_ao[2][B*N*INNER];
__device__ float g_ppart[16][B*QD];
__device__ float g_pooled[B*QD];
__device__ int g_gidx[B*NKP];     // dense -> orig
__device__ int g_scat[B*NKP];     // orig -> dense (or -1)
__device__ int g_nvalid[B];

// ---------------- helpers ----------------
__device__ __forceinline__ uint32_t sm_u32(const void* p){
    uint32_t a;
    asm("{ .reg .u64 t; cvta.to.shared.u64 t, %1; cvt.u32.u64 %0, t; }" : "=r"(a) : "l"(p));
    return a;
}
__device__ __forceinline__ void ldmx4(uint32_t* r, uint32_t addr){
    asm volatile("ldmatrix.sync.aligned.m8n8.x4.shared.b16 {%0,%1,%2,%3}, [%4];"
        : "=r"(r[0]), "=r"(r[1]), "=r"(r[2]), "=r"(r[3]) : "r"(addr));
}
__device__ __forceinline__ void mma16816(float* d, const uint32_t* a, const uint32_t* b){
    asm volatile("mma.sync.aligned.m16n8k16.row.col.f32.bf16.bf16.f32 "
        "{%0,%1,%2,%3}, {%4,%5,%6,%7}, {%8,%9}, {%0,%1,%2,%3};"
        : "+f"(d[0]), "+f"(d[1]), "+f"(d[2]), "+f"(d[3])
        : "r"(a[0]), "r"(a[1]), "r"(a[2]), "r"(a[3]), "r"(b[0]), "r"(b[1]));
}
#define CP_ASYNC(dst, src) \
    asm volatile("cp.async.cg.shared.global [%0], [%1], 16;" :: "r"(dst), "l"(src))
#define CP_COMMIT() asm volatile("cp.async.commit_group;" ::: "memory")
#define CP_WAIT3()  asm volatile("cp.async.wait_group 3;" ::: "memory")
#define CP_WAIT2()  asm volatile("cp.async.wait_group 2;" ::: "memory")
#define CP_WAIT1()  asm volatile("cp.async.wait_group 1;" ::: "memory")
#define CP_WAIT0()  asm volatile("cp.async.wait_group 0;" ::: "memory")

__device__ __forceinline__ uint32_t packbf(float a, float b){
    uint32_t r;
    asm("cvt.rn.bf16x2.f32 %0, %1, %2;" : "=r"(r) : "f"(b), "f"(a));
    return r;
}
__device__ __forceinline__ uint32_t packbf_lo(float a, float b, uint32_t hi){
    float hx = __uint_as_float((hi & 0xFFFFu) << 16);
    float hy = __uint_as_float(hi & 0xFFFF0000u);
    return packbf(a - hx, b - hy);
}
__device__ __forceinline__ float fexp(float x){
    float t = fmaxf(x * 1.4426950409f, -120.f);
    float r = rintf(t);
    float f = t - r;
    float p = 1.33336e-3f;
    p = fmaf(p, f, 9.61812e-3f);
    p = fmaf(p, f, 5.55041e-2f);
    p = fmaf(p, f, 2.4022651e-1f);
    p = fmaf(p, f, 6.9314718e-1f);
    p = fmaf(p, f, 1.0f);
    return p * __int_as_float(((int)r + 127) << 23);
}

// ---------------- mask scan ----------------
__global__ void scan_kernel(const unsigned char* __restrict__ m){
    __shared__ int anynz;
    __shared__ int sc[256];
    int tid = threadIdx.x, b = blockIdx.x;
    if (tid == 0) anynz = 0;
    __syncthreads();
    int loc = 0;
    for (int i = tid; i < 8192; i += 256)
        if ((i & 3) && m[i]) loc = 1;
    if (loc) atomicOr(&anynz, 1);
    __syncthreads();
    bool u8 = (anynz != 0);
    const int* mi = (const int*)m;

    int base = tid * 17, c = 0;
    unsigned int bits = 0;
    #pragma unroll
    for (int e = 0; e < 17; e++){
        int w = base + e;
        int on = 0;
        if (w < NK) on = u8 ? (m[b*NK + w] != 0) : (mi[b*NK + w] != 0);
        bits |= (unsigned)on << e;
        c += on;
    }
    sc[tid] = c;
    __syncthreads();
    for (int off = 1; off < 256; off <<= 1){
        int v = (tid >= off) ? sc[tid - off] : 0;
        __syncthreads();
        sc[tid] += v;
        __syncthreads();
    }
    int pos = sc[tid] - c;
    #pragma unroll
    for (int e = 0; e < 17; e++){
        int w = base + e;
        if (w < NKP){
            if ((bits >> e) & 1){
                g_gidx[b*NKP + pos] = w;
                g_scat[b*NKP + w] = pos;
                pos++;
            } else {
                g_scat[b*NKP + w] = -1;
            }
        }
    }
    __syncthreads();
    int nvv = sc[255];
    if (tid == 0) g_nvalid[b] = nvv;
    for (int i = nvv + tid; i < NKP; i += 256) g_gidx[b*NKP + i] = 0;
}

// ---------------- pooled mean ----------------
__global__ void pooled_p1(const float* __restrict__ x){
    int id = blockIdx.x*256 + threadIdx.x;
    int chunk = blockIdx.y;
    int b = id / QD, d = id % QD;
    const float* p = x + (size_t)b*N*QD + (size_t)chunk*256*QD + d;
    float s = 0.f;
    #pragma unroll 8
    for (int n = 0; n < 256; n++) s += p[(size_t)n*QD];
    g_ppart[chunk][id] = s;
}
__global__ void pooled_p2(){
    int id = blockIdx.x*256 + threadIdx.x;
    if (id >= B*QD) return;
    float s = 0.f;
    #pragma unroll
    for (int c = 0; c < 16; c++) s += g_ppart[c][id];
    g_pooled[id] = s * (1.0f/N);
}

__global__ void bg_kernel(const float* __restrict__ Wkbg, const float* __restrict__ Wvbg){
    int id = blockIdx.x*256 + threadIdx.x;
    if (id >= B*INNER) return;
    int b = id / INNER, o = id % INNER;
    int pos = g_scat[b*NKP + N];
    if (pos < 0) return;
    float sk = 0.f, sv = 0.f;
    for (int k = 0; k < QD; k++){
        float pv = g_pooled[b*QD + k];
        sk += pv * Wkbg[(size_t)k*INNER + o];
        sv += pv * Wvbg[(size_t)k*INNER + o];
    }
    size_t kb = (size_t)(b*NKP + pos)*INNER + o;
    bf h;
    h = __float2bfloat16(sk); g_kd[0][kb] = h; g_kd[1][kb] = __float2bfloat16(sk - __bfloat162float(h));
    h = __float2bfloat16(sv); g_vd[0][kb] = h; g_vd[1][kb] = __float2bfloat16(sv - __bfloat162float(h));
}

__global__ void pack_split(const float4* __restrict__ src, bf* __restrict__ hi, bf* __restrict__ lo, int n4){
    int i = blockIdx.x*256 + threadIdx.x;
    if (i >= n4) return;
    float4 v = src[i];
    uint32_t h0 = packbf(v.x, v.y), h1 = packbf(v.z, v.w);
    uint32_t l0 = packbf_lo(v.x, v.y, h0), l1 = packbf_lo(v.z, v.w, h1);
    ((uint2*)hi)[i] = make_uint2(h0, h1);
    ((uint2*)lo)[i] = make_uint2(l0, l1);
}

__global__ void packT(const float* __restrict__ src, bf* __restrict__ hi, bf* __restrict__ lo, int R, int C){
    __shared__ float t[32][33];
    int c0 = blockIdx.x*32, r0 = blockIdx.y*32;
    for (int i = threadIdx.y; i < 32; i += 8)
        t[i][threadIdx.x] = src[(size_t)(r0+i)*C + c0 + threadIdx.x];
    __syncthreads();
    for (int i = threadIdx.y; i < 32; i += 8){
        float v = t[threadIdx.x][i];
        size_t o = (size_t)(c0+i)*R + r0 + threadIdx.x;
        bf h = __float2bfloat16(v);
        hi[o] = h; lo[o] = __float2bfloat16(v - __bfloat162float(h));
    }
}

// transpose dense v -> g_vt; zero tail (>= nvalid)
__global__ void vtrans_kernel(){
    __shared__ bf t[2][32][33];
    int z = blockIdx.z, b = z >> 3, h = z & 7;
    int j0 = blockIdx.x*32, d0 = blockIdx.y*32;
    int tx = threadIdx.x, ty = threadIdx.y;
    int nv = g_nvalid[b];
    #pragma unroll
    for (int s = 0; s < 2; s++)
        for (int i = ty; i < 32; i += 8){
            int jd = j0 + i;
            bf val = __float2bfloat16(0.f);
            if (jd < nv)
                val = g_vd[s][(size_t)(b*NKP + jd)*INNER + h*64 + d0 + tx];
            t[s][i][tx] = val;
        }
    __syncthreads();
    #pragma unroll
    for (int s = 0; s < 2; s++)
        for (int i = ty; i < 32; i += 8)
            g_vt[s][((size_t)z*DH + d0 + i)*NKP + j0 + tx] = t[s][tx][i];
}

// ---------------- fused flash attention (64-q tile, 2 CTAs/SM) ----------------
#define FSP 72
#define FTB (64*FSP*2)
#define FSTG (4*FTB)
#define FSMEM (2*FTB + 2*FSTG + 128)

__global__ __launch_bounds__(128, 2) void flash_kernel(){
    extern __shared__ __align__(16) char fsm[];
    const int tid = threadIdx.x, wid = tid >> 5, lane = tid & 31;
    const int z = blockIdx.y, b = z >> 3, h = z & 7;
    const int q0 = blockIdx.x*64;
    uint32_t sb = sm_u32(fsm);
    const uint32_t oQ = 0, oS = 2*FTB;

    const int nv = g_nvalid[b];
    const int ntiles = (nv + 63) >> 6;

    const bf* Qg[2] = { g_q[0] + ((size_t)(b*N + q0))*INNER + h*64,
                        g_q[1] + ((size_t)(b*N + q0))*INNER + h*64 };
    const bf* Kg[2] = { g_kd[0] + (size_t)b*NKP*INNER + h*64,
                        g_kd[1] + (size_t)b*NKP*INNER + h*64 };
    const bf* Vg[2] = { g_vt[0] + (size_t)z*DH*NKP,
                        g_vt[1] + (size_t)z*DH*NKP };

    auto load_stage = [&](int t){
        int j0 = t*64;
        uint32_t st = sb + oS + (t & 1)*FSTG;
        #pragma unroll 4
        for (int u = tid; u < 2048; u += 128){
            int tile = u >> 9, r = (u >> 3) & 63, sg = u & 7;
            const bf* src;
            if (tile == 0)      src = Kg[0] + (size_t)(j0 + r)*INNER + sg*8;
            else if (tile == 1) src = Kg[1] + (size_t)(j0 + r)*INNER + sg*8;
            else if (tile == 2) src = Vg[0] + (size_t)r*NKP + j0 + sg*8;
            else                src = Vg[1] + (size_t)r*NKP + j0 + sg*8;
            CP_ASYNC(st + tile*FTB + (uint32_t)(r*FSP + sg*8)*2, src);
        }
    };

    #pragma unroll 4
    for (int u = tid; u < 1024; u += 128){
        int half = u >> 9, r = (u >> 3) & 63, sg = u & 7;
        CP_ASYNC(sb + oQ + half*FTB + (uint32_t)(r*FSP + sg*8)*2,
                 Qg[half] + (size_t)r*INNER + sg*8);
    }
    if (ntiles > 0) load_stage(0);
    CP_COMMIT();
    if (ntiles > 1) load_stage(1);
    CP_COMMIT();

    uint32_t aQh[4][4], aQl[4][4];
    float lacc0 = 0.f, lacc1 = 0.f;
    float o[8][4];
    #pragma unroll
    for (int i = 0; i < 8; i++){ o[i][0]=0.f; o[i][1]=0.f; o[i][2]=0.f; o[i][3]=0.f; }

    const int gg = lane >> 3, ii = lane & 7, tq = lane & 3;

    for (int t = 0; t < ntiles; t++){
        if (t + 2 < ntiles) CP_WAIT1(); else CP_WAIT0();
        __syncthreads();

        if (t == 0){
            int row = wid*16 + (lane & 15);
            int col = (lane >> 4)*8;
            #pragma unroll
            for (int ks = 0; ks < 4; ks++){
                uint32_t ad = sb + oQ + (uint32_t)(row*FSP + ks*16 + col)*2;
                ldmx4(aQh[ks], ad);
                ldmx4(aQl[ks], ad + FTB);
            }
        }

        uint32_t st = sb + oS + (t & 1)*FSTG;

        float s[8][4];
        #pragma unroll
        for (int i = 0; i < 8; i++){ s[i][0]=0.f; s[i][1]=0.f; s[i][2]=0.f; s[i][3]=0.f; }
        #pragma unroll
        for (int ks = 0; ks < 4; ks++){
            #pragma unroll
            for (int p = 0; p < 4; p++){
                int rn = p*16 + (gg >> 1)*8 + ii;
                int ck = ks*16 + (gg & 1)*8;
                uint32_t off = (uint32_t)(rn*FSP + ck)*2;
                uint32_t bh[4], bl[4];
                ldmx4(bh, st + off);
                ldmx4(bl, st + FTB + off);
                mma16816(s[2*p],   aQh[ks], bh);
                mma16816(s[2*p],   aQh[ks], bl);
                mma16816(s[2*p],   aQl[ks], bh);
                mma16816(s[2*p+1], aQh[ks], bh + 2);
                mma16816(s[2*p+1], aQh[ks], bl + 2);
                mma16816(s[2*p+1], aQl[ks], bh + 2);
            }
        }

        int jb = t*64;
        #pragma unroll
        for (int nt = 0; nt < 8; nt++){
            int c0 = jb + nt*8 + tq*2;
            bool k0 = c0 < nv, k1 = (c0 + 1) < nv;
            s[nt][0] = fexp(k0 ? s[nt][0]*0.125f : -1e30f);
            s[nt][1] = fexp(k1 ? s[nt][1]*0.125f : -1e30f);
            s[nt][2] = fexp(k0 ? s[nt][2]*0.125f : -1e30f);
            s[nt][3] = fexp(k1 ? s[nt][3]*0.125f : -1e30f);
            lacc0 += s[nt][0] + s[nt][1];
            lacc1 += s[nt][2] + s[nt][3];
        }

        #pragma unroll
        for (int ks = 0; ks < 4; ks++){
            uint32_t aPh[4], aPl[4];
            aPh[0] = packbf(s[2*ks][0],   s[2*ks][1]);
            aPh[1] = packbf(s[2*ks][2],   s[2*ks][3]);
            aPh[2] = packbf(s[2*ks+1][0], s[2*ks+1][1]);
            aPh[3] = packbf(s[2*ks+1][2], s[2*ks+1][3]);
            aPl[0] = packbf_lo(s[2*ks][0],   s[2*ks][1],   aPh[0]);
            aPl[1] = packbf_lo(s[2*ks][2],   s[2*ks][3],   aPh[1]);
            aPl[2] = packbf_lo(s[2*ks+1][0], s[2*ks+1][1], aPh[2]);
            aPl[3] = packbf_lo(s[2*ks+1][2], s[2*ks+1][3], aPh[3]);
            #pragma unroll
            for (int dp = 0; dp < 4; dp++){
                int rn = dp*16 + (gg >> 1)*8 + ii;
                int ck = ks*16 + (gg & 1)*8;
                uint32_t off = (uint32_t)(rn*FSP + ck)*2;
                uint32_t vh[4], vl[4];
                ldmx4(vh, st + 2*FTB + off);
                ldmx4(vl, st + 3*FTB + off);
                mma16816(o[2*dp],   aPh, vh);
                mma16816(o[2*dp],   aPh, vl);
                mma16816(o[2*dp],   aPl, vh);
                mma16816(o[2*dp+1], aPh, vh + 2);
                mma16816(o[2*dp+1], aPh, vl + 2);
                mma16816(o[2*dp+1], aPl, vh + 2);
            }
        }
        __syncthreads();
        if (t + 2 < ntiles){ load_stage(t + 2); CP_COMMIT(); }
    }

    lacc0 += __shfl_xor_sync(~0u, lacc0, 1); lacc0 += __shfl_xor_sync(~0u, lacc0, 2);
    lacc1 += __shfl_xor_sync(~0u, lacc1, 1); lacc1 += __shfl_xor_sync(~0u, lacc1, 2);
    float inv0 = 1.0f / lacc0, inv1 = 1.0f / lacc1;

    int g = lane >> 2;
    int row0 = q0 + wid*16 + g, row1 = row0 + 8;
    ll base0 = ((ll)(b*N) + row0)*INNER + h*64;
    ll base1 = ((ll)(b*N) + row1)*INNER + h*64;
    #pragma unroll
    for (int nt = 0; nt < 8; nt++){
        int c = nt*8 + tq*2;
        float v0 = o[nt][0]*inv0, v1 = o[nt][1]*inv0;
        float v2 = o[nt][2]*inv1, v3 = o[nt][3]*inv1;
        uint32_t h0 = packbf(v0, v1), l0p = packbf_lo(v0, v1, h0);
        uint32_t h1 = packbf(v2, v3), l1p = packbf_lo(v2, v3, h1);
        *(uint32_t*)(g_ao[0] + base0 + c) = h0;
        *(uint32_t*)(g_ao[1] + base0 + c) = l0p;
        *(uint32_t*)(g_ao[0] + base1 + c) = h1;
        *(uint32_t*)(g_ao[1] + base1 + c) = l1p;
    }
}

// ---------------- warp-mma split-bf16 GEMM (4-stage cp.async pipeline) ----------------
struct GemmArgs {
    const bf *Ah, *Al, *Bh, *Bl;
    int K, lda, ldb;
    float* Cf; const float* bias;
    bf *Ch, *Cl;
    int ldc, remap, gathered;
};

template<int NTILE>
__global__ __launch_bounds__(256, 1) void gemm_mma(GemmArgs g){
    constexpr int KC = 32, KPAD = 40;
    constexpr int WGM = 2;
    constexpr int WM = 64;
    constexpr int WN = NTILE / 4;
    constexpr int MT = 4, NT = WN / 8;
    constexpr int ASZ = 128 * KPAD * 2;
    constexpr int BSZ = NTILE * KPAD * 2;
    constexpr int STAGE = 2*ASZ + 2*BSZ;      // 40960 for NTILE=128
    constexpr int TOT = 1024 + NTILE*8;

    extern __shared__ __align__(16) char smem[];
    __shared__ ll rowoff[128];
    __shared__ int rowok[128];
    uint32_t sbase = sm_u32(smem);

    int tid = threadIdx.x, wid = tid >> 5, lane = tid & 31;
    int wm = wid % WGM, wn = wid / WGM;

    int bb = 0, m0 = 0;
    if (g.gathered){
        bb = blockIdx.y / 33;
        m0 = (blockIdx.y % 33) * 128;
        int nvv = g_nvalid[bb];
        if (m0 >= nvv) return;
        if (tid < 128){
            int i = m0 + tid;
            int src = (i < nvv) ? g_gidx[bb*NKP + i] : 0;
            int ok = (i < nvv) && (src != N);
            if (src >= N) src = 0;
            rowoff[tid] = ((ll)bb*N + src) * g.lda;
            rowok[tid] = ok;
        }
        __syncthreads();
    }

    const bf* pAh = g.Ah;
    const bf* pAl = g.Al;
    const bf* pBh = g.Bh + (ll)blockIdx.x*NTILE*g.ldb;
    const bf* pBl = g.Bl + (ll)blockIdx.x*NTILE*g.ldb;
    const ll arow0 = (ll)blockIdx.y*128;

    float acc[MT][NT][4];
    #pragma unroll
    for (int i = 0; i < MT; i++)
        #pragma unroll
        for (int j = 0; j < NT; j++)
            #pragma unroll
            for (int e = 0; e < 4; e++) acc[i][j][e] = 0.f;

    int nch = g.K / KC;

    auto load_chunk = [&](int c){
        int k0 = c * KC;
        uint32_t st = sbase + (uint32_t)(c & 3)*STAGE;
        if (g.gathered){
            #pragma unroll 2
            for (int u = tid; u < TOT; u += 256){
                const bf* src; uint32_t doff; int rel, isA;
                if (u < 512)              { rel = u;              src = pAh; doff = 0;         isA = 1; }
                else if (u < 1024)        { rel = u - 512;        src = pAl; doff = ASZ;       isA = 1; }
                else if (u < 1024+NTILE*4){ rel = u - 1024;       src = pBh; doff = 2*ASZ;     isA = 0; }
                else                      { rel = u-1024-NTILE*4; src = pBl; doff = 2*ASZ+BSZ; isA = 0; }
                int r = rel >> 2, sg = rel & 3;
                const bf* gs = isA ? (src + rowoff[r] + k0 + sg*8)
                                   : (src + (ll)r*g.ldb + k0 + sg*8);
                CP_ASYNC(st + doff + (uint32_t)(r*KPAD + sg*8)*2, gs);
            }
        } else {
            #pragma unroll 2
            for (int u = tid; u < TOT; u += 256){
                const bf* src; uint32_t doff; int rel, isA;
                if (u < 512)              { rel = u;              src = pAh; doff = 0;         isA = 1; }
                else if (u < 1024)        { rel = u - 512;        src = pAl; doff = ASZ;       isA = 1; }
                else if (u < 1024+NTILE*4){ rel = u - 1024;       src = pBh; doff = 2*ASZ;     isA = 0; }
                else                      { rel = u-1024-NTILE*4; src = pBl; doff = 2*ASZ+BSZ; isA = 0; }
                int r = rel >> 2, sg = rel & 3;
                const bf* gs = isA ? (src + (arow0 + r)*g.lda + k0 + sg*8)
                                   : (src + (ll)r*g.ldb + k0 + sg*8);
                CP_ASYNC(st + doff + (uint32_t)(r*KPAD + sg*8)*2, gs);
            }
        }
        CP_COMMIT();
    };

    // 4-stage prologue
    load_chunk(0);
    load_chunk(1);
    load_chunk(2);

    for (int c = 0; c < nch; c++){
        if (c + 3 < nch){ load_chunk(c + 3); CP_WAIT3(); }
        else if (c + 2 < nch) CP_WAIT2();
        else if (c + 1 < nch) CP_WAIT1();
        else CP_WAIT0();
        __syncthreads();

        uint32_t stg = sbase + (uint32_t)(c & 3)*STAGE;
        #pragma unroll
        for (int ks = 0; ks < 2; ks++){
            int kb = ks * 16;
            uint32_t aH[MT][4], aL[MT][4];
            #pragma unroll
            for (int mt = 0; mt < MT; mt++){
                int row = wm*WM + mt*16 + (lane & 15);
                int col = kb + (lane >> 4)*8;
                uint32_t ad = stg + (uint32_t)(row*KPAD + col)*2;
                ldmx4(aH[mt], ad);
                ldmx4(aL[mt], ad + ASZ);
            }
            #pragma unroll
            for (int p = 0; p < NT/2; p++){
                int gg = lane >> 3, ii = lane & 7;
                int row = wn*WN + p*16 + (gg >> 1)*8 + ii;
                int col = kb + (gg & 1)*8;
                uint32_t bd = stg + 2*ASZ + (uint32_t)(row*KPAD + col)*2;
                uint32_t bH[4], bL[4];
                ldmx4(bH, bd);
                ldmx4(bL, bd + BSZ);
                #pragma unroll
                for (int mt = 0; mt < MT; mt++){
                    mma16816(acc[mt][2*p],   aH[mt], bH);
                    mma16816(acc[mt][2*p],   aH[mt], bL);
                    mma16816(acc[mt][2*p],   aL[mt], bH);
                    mma16816(acc[mt][2*p+1], aH[mt], bH + 2);
                    mma16816(acc[mt][2*p+1], aH[mt], bL + 2);
                    mma16816(acc[mt][2*p+1], aL[mt], bH + 2);
                }
            }
        }
        __syncthreads();
    }

    int ncb = blockIdx.x*NTILE + wn*WN;
    #pragma unroll
    for (int mt = 0; mt < MT; mt++){
        #pragma unroll
        for (int hf = 0; hf < 2; hf++){
            int lrow = wm*WM + mt*16 + (lane >> 2) + hf*8;
            ll orow; bool wr = true;
            if (g.gathered){
                wr = rowok[lrow] != 0;
                orow = (ll)bb*NKP + m0 + lrow;
            } else {
                int row = blockIdx.y*128 + lrow;
                orow = (ll)(row >> 12)*g.remap + (row & 4095);
            }
            if (!wr) continue;
            ll basei = orow*(ll)g.ldc + ncb;
            #pragma unroll
            for (int nt = 0; nt < NT; nt++){
                int cl = nt*8 + (lane & 3)*2;
                float v0 = acc[mt][nt][hf*2], v1 = acc[mt][nt][hf*2+1];
                if (g.Cf){
                    if (g.bias){ v0 += g.bias[ncb + cl]; v1 += g.bias[ncb + cl + 1]; }
                    float2 f2; f2.x = v0; f2.y = v1;
                    *(float2*)(g.Cf + basei + cl) = f2;
                } else {
                    uint32_t hh = packbf(v0, v1);
                    uint32_t lo = packbf_lo(v0, v1, hh);
                    *(uint32_t*)(g.Ch + basei + cl) = hh;
                    *(uint32_t*)(g.Cl + basei + cl) = lo;
                }
            }
        }
    }
}

// ---------------- launch ----------------
extern "C" void kernel_launch(void* const* d_in, const int* in_sizes, int n_in,
                              void* d_out, int out_size){
    const float* x    = (const float*)d_in[0];
    const float* ctx  = (const float*)d_in[1];
    const unsigned char* mask = (const unsigned char*)d_in[2];
    const float* Wq   = (const float*)d_in[3];
    const float* Wk   = (const float*)d_in[4];
    const float* Wv   = (const float*)d_in[5];
    const float* Wkbg = (const float*)d_in[6];
    const float* Wvbg = (const float*)d_in[7];
    const float* Wout = (const float*)d_in[8];
    const float* bout = (const float*)d_in[9];
    float* out = (float*)d_out;

    bf *xs, *cs, *wq, *wk, *wv, *wo, *q, *kd, *vd, *ao;
    cudaGetSymbolAddress((void**)&xs, g_xs);
    cudaGetSymbolAddress((void**)&cs, g_cs);
    cudaGetSymbolAddress((void**)&wq, g_wq);
    cudaGetSymbolAddress((void**)&wk, g_wk);
    cudaGetSymbolAddress((void**)&wv, g_wv);
    cudaGetSymbolAddress((void**)&wo, g_wo);
    cudaGetSymbolAddress((void**)&q,  g_q);
    cudaGetSymbolAddress((void**)&kd, g_kd);
    cudaGetSymbolAddress((void**)&vd, g_vd);
    cudaGetSymbolAddress((void**)&ao, g_ao);
    const size_t XSZ = (size_t)B*N*QD, QSZ = (size_t)B*N*INNER;
    const size_t KSZ = (size_t)B*NKP*INNER;
    const size_t WSZ = (size_t)QD*INNER;

    const int SM128 = 4*(2*128*40*2 + 2*128*40*2)/2;   // 4 stages x 40960 = 163840
    cudaFuncSetAttribute(gemm_mma<128>, cudaFuncAttributeMaxDynamicSharedMemorySize, 163840);
    cudaFuncSetAttribute(flash_kernel,  cudaFuncAttributeMaxDynamicSharedMemorySize, FSMEM);
    (void)SM128;

    scan_kernel<<<B, 256>>>(mask);
    pooled_p1<<<dim3(B*QD/256, 16), 256>>>(x);
    pooled_p2<<<(B*QD + 255)/256, 256>>>();
    pack_split<<<(int)((XSZ/4 + 255)/256), 256>>>((const float4*)x,   xs, xs + XSZ, (int)(XSZ/4));
    pack_split<<<(int)((XSZ/4 + 255)/256), 256>>>((const float4*)ctx, cs, cs + XSZ, (int)(XSZ/4));
    packT<<<dim3(INNER/32, QD/32),    dim3(32, 8)>>>(Wq,   wq, wq + WSZ, QD, INNER);
    packT<<<dim3(INNER/32, QD/32),    dim3(32, 8)>>>(Wk,   wk, wk + WSZ, CD, INNER);
    packT<<<dim3(INNER/32, QD/32),    dim3(32, 8)>>>(Wv,   wv, wv + WSZ, CD, INNER);
    packT<<<dim3(QD/32,    INNER/32), dim3(32, 8)>>>(Wout, wo, wo + WSZ, INNER, QD);
    bg_kernel<<<(B*INNER + 255)/256, 256>>>(Wkbg, Wvbg);

    GemmArgs a;
    // q = x @ Wq (full, direct addressing)
    a = { xs, xs + XSZ, wq, wq + WSZ, QD, QD, QD,
          nullptr, nullptr, q, q + QSZ, INNER, 4096, 0 };
    gemm_mma<128><<<dim3(INNER/128, (B*N)/128, 1), 256, 163840>>>(a);
    // k = gather(ctx) @ Wk  (dense keys only)
    a = { cs, cs + XSZ, wk, wk + WSZ, CD, CD, CD,
          nullptr, nullptr, kd, kd + KSZ, INNER, NKP, 1 };
    gemm_mma<128><<<dim3(INNER/128, B*33, 1), 256, 163840>>>(a);
    // v = gather(ctx) @ Wv  (dense keys only)
    a = { cs, cs + XSZ, wv, wv + WSZ, CD, CD, CD,
          nullptr, nullptr, vd, vd + KSZ, INNER, NKP, 1 };
    gemm_mma<128><<<dim3(INNER/128, B*33, 1), 256, 163840>>>(a);
    // vT (transpose dense, zero tail)
    vtrans_kernel<<<dim3(NKP/32, DH/32, B*H), dim3(32, 8)>>>();
    // fused attention (64-q tiles, 2 CTAs/SM)
    flash_kernel<<<dim3(N/64, B*H), 128, FSMEM>>>();
    // out = ao @ Wout + b
    a = { ao, ao + QSZ, wo, wo + WSZ, INNER, INNER, INNER,
          out, bout, nullptr, nullptr, QD, 4096, 0 };
    gemm_mma<128><<<dim3(QD/128, (B*N)/128, 1), 256, 163840>>>(a);
}